// round 2
// baseline (speedup 1.0000x reference)
#include <cuda_runtime.h>
#include <math.h>

#define DIM 512
#define BM 128
#define BN 128
#define BK 16
#define TM 8
#define TN 8
#define P_MAX 2048
#define R_MAX 65536

// Scratch (no allocations allowed): norms + global min (encoded as ordered uint).
__device__ float g_xn[P_MAX];
__device__ float g_yn[R_MAX];
__device__ unsigned int g_min_bits;

// Monotone float <-> uint encoding so atomicMin(uint) orders floats correctly
// (handles the slightly-negative sq values from cancellation).
__device__ __forceinline__ unsigned int enc_f(float f) {
    unsigned int u = __float_as_uint(f);
    return (u & 0x80000000u) ? ~u : (u | 0x80000000u);
}
__device__ __forceinline__ float dec_f(unsigned int u) {
    return (u & 0x80000000u) ? __uint_as_float(u & 0x7FFFFFFFu)
                             : __uint_as_float(~u);
}

// Kernel 0: reset the global min and compute row norms for x and y.
__global__ void norms_kernel(const float* __restrict__ x,
                             const float* __restrict__ y,
                             int P, int R) {
    int row = blockIdx.x * blockDim.x + threadIdx.x;
    if (row == 0) g_min_bits = 0xFFFFFFFFu;  // enc(+inf-ish): max uint
    int total = P + R;
    if (row >= total) return;
    const float* src = (row < P) ? (x + (size_t)row * DIM)
                                 : (y + (size_t)(row - P) * DIM);
    const float4* s4 = reinterpret_cast<const float4*>(src);
    float acc = 0.f;
#pragma unroll 8
    for (int i = 0; i < DIM / 4; i++) {
        float4 v = s4[i];
        acc += v.x * v.x + v.y * v.y + v.z * v.z + v.w * v.w;
    }
    if (row < P) g_xn[row] = acc;
    else         g_yn[row - P] = acc;
}

// Kernel 1: tiled "GEMM" computing dot(x_p, y_r); epilogue forms
// sq = |x|^2 + |y|^2 - 2*dot and block-reduces the min into g_min_bits.
__global__ void __launch_bounds__(256, 2)
min_dist_kernel(const float* __restrict__ x,
                const float* __restrict__ y,
                int P, int R) {
    __shared__ float As[BK][BM];  // transposed x tile: As[k][m]
    __shared__ float Bs[BK][BN];  // transposed y tile: Bs[k][n]

    const int bm = blockIdx.y * BM;   // offset into P
    const int bn = blockIdx.x * BN;   // offset into R
    const int tid = threadIdx.x;
    const int tx = tid % (BN / TN);   // 0..15  (N direction)
    const int ty = tid / (BN / TN);   // 0..15  (M direction)

    float acc[TM][TN];
#pragma unroll
    for (int i = 0; i < TM; i++)
#pragma unroll
        for (int j = 0; j < TN; j++) acc[i][j] = 0.f;

    for (int k0 = 0; k0 < DIM; k0 += BK) {
        // Load x tile: BM x BK = 2048 floats = 512 float4; 2 per thread.
#pragma unroll
        for (int l = 0; l < 2; l++) {
            int j = tid + l * 256;           // 0..511
            int row = j >> 2;                // 0..127
            int c4  = (j & 3) * 4;           // 0,4,8,12
            float4 v = *reinterpret_cast<const float4*>(
                x + (size_t)(bm + row) * DIM + k0 + c4);
            As[c4 + 0][row] = v.x;
            As[c4 + 1][row] = v.y;
            As[c4 + 2][row] = v.z;
            As[c4 + 3][row] = v.w;
        }
        // Load y tile: BN x BK, same layout.
#pragma unroll
        for (int l = 0; l < 2; l++) {
            int j = tid + l * 256;
            int row = j >> 2;
            int c4  = (j & 3) * 4;
            float4 v = *reinterpret_cast<const float4*>(
                y + (size_t)(bn + row) * DIM + k0 + c4);
            Bs[c4 + 0][row] = v.x;
            Bs[c4 + 1][row] = v.y;
            Bs[c4 + 2][row] = v.z;
            Bs[c4 + 3][row] = v.w;
        }
        __syncthreads();

#pragma unroll
        for (int k = 0; k < BK; k++) {
            float ra[TM], rb[TN];
            *reinterpret_cast<float4*>(&ra[0]) =
                *reinterpret_cast<const float4*>(&As[k][ty * TM]);
            *reinterpret_cast<float4*>(&ra[4]) =
                *reinterpret_cast<const float4*>(&As[k][ty * TM + 4]);
            *reinterpret_cast<float4*>(&rb[0]) =
                *reinterpret_cast<const float4*>(&Bs[k][tx * TN]);
            *reinterpret_cast<float4*>(&rb[4]) =
                *reinterpret_cast<const float4*>(&Bs[k][tx * TN + 4]);
#pragma unroll
            for (int i = 0; i < TM; i++)
#pragma unroll
                for (int j = 0; j < TN; j++)
                    acc[i][j] = fmaf(ra[i], rb[j], acc[i][j]);
        }
        __syncthreads();
    }

    // Epilogue: sq = xn + yn - 2*dot; thread-local min.
    float xnr[TM], ynr[TN];
#pragma unroll
    for (int i = 0; i < TM; i++) xnr[i] = g_xn[bm + ty * TM + i];
#pragma unroll
    for (int j = 0; j < TN; j++) ynr[j] = g_yn[bn + tx * TN + j];

    float m = 3.4e38f;
#pragma unroll
    for (int i = 0; i < TM; i++)
#pragma unroll
        for (int j = 0; j < TN; j++) {
            float sq = fmaf(-2.0f, acc[i][j], xnr[i] + ynr[j]);
            m = fminf(m, sq);
        }

    // Warp reduce, then one atomic per warp (8 per block; contention negligible).
#pragma unroll
    for (int off = 16; off > 0; off >>= 1)
        m = fminf(m, __shfl_xor_sync(0xFFFFFFFFu, m, off));
    if ((tid & 31) == 0)
        atomicMin(&g_min_bits, enc_f(m));
}

// Kernel 2: finalize -> sqrt(max(min_sq, 0))
__global__ void finalize_kernel(float* __restrict__ out) {
    float sq = dec_f(g_min_bits);
    out[0] = sqrtf(fmaxf(sq, 0.0f));
}

extern "C" void kernel_launch(void* const* d_in, const int* in_sizes, int n_in,
                              void* d_out, int out_size) {
    const float* x = (const float*)d_in[0];  // [1, P, 512]
    const float* y = (const float*)d_in[1];  // [1, R, 512]
    int P = in_sizes[0] / DIM;
    int R = in_sizes[1] / DIM;

    int total = P + R;
    norms_kernel<<<(total + 255) / 256, 256>>>(x, y, P, R);

    dim3 grid(R / BN, P / BM);  // (512, 16) for the fixed shapes
    min_dist_kernel<<<grid, 256>>>(x, y, P, R);

    finalize_kernel<<<1, 1>>>((float*)d_out);
}

// round 4
// speedup vs baseline: 8.2874x; 8.2874x over previous
#include <cuda_runtime.h>
#include <cuda_bf16.h>
#include <math.h>
#include <stdint.h>

#define DIM 512
#define P_MAX 2048
#define R_MAX 65536
#define BM 128
#define BN 128
#define BK 64                 // bf16 elems per chunk = 128 bytes/row
#define NCHUNK (DIM / BK)     // 8
#define STAGES 3
#define A_BYTES (BM * 128)    // 16384
#define B_BYTES (BN * 128)    // 16384
#define STAGE_BYTES (A_BYTES + B_BYTES)          // 32768
#define SOFF_XN (STAGES * STAGE_BYTES)           // 98304
#define SOFF_YN (SOFF_XN + BM * 4)
#define SMEM_BYTES (SOFF_YN + BN * 4)            // 99328 -> 2 CTAs/SM

// Scratch (no allocations allowed)
__device__ __nv_bfloat16 g_A[P_MAX * DIM];   // 2 MB
__device__ __nv_bfloat16 g_B[R_MAX * DIM];   // 64 MB
__device__ float g_xn[P_MAX];
__device__ float g_yn[R_MAX];
__device__ unsigned int g_min_bits;

// ---------------- helpers ----------------
__device__ __forceinline__ unsigned int enc_f(float f) {
    unsigned int u = __float_as_uint(f);
    return (u & 0x80000000u) ? ~u : (u | 0x80000000u);
}
__device__ __forceinline__ float dec_f(unsigned int u) {
    return (u & 0x80000000u) ? __uint_as_float(u & 0x7FFFFFFFu)
                             : __uint_as_float(~u);
}
__device__ __forceinline__ uint32_t smem_u32(const void* p) {
    uint32_t a;
    asm("{ .reg .u64 t; cvta.to.shared.u64 t, %1; cvt.u32.u64 %0, t; }"
        : "=r"(a) : "l"(p));
    return a;
}
__device__ __forceinline__ void cp16(uint32_t dst, const void* src) {
    asm volatile("cp.async.cg.shared.global [%0], [%1], 16;"
                 :: "r"(dst), "l"(src) : "memory");
}
__device__ __forceinline__ uint32_t swz(uint32_t off) {
    return off ^ ((off >> 3) & 0x70);   // SW128 within 1KB atom (128B rows)
}
__device__ __forceinline__ void ldsm_x4(uint32_t& r0, uint32_t& r1,
                                        uint32_t& r2, uint32_t& r3,
                                        uint32_t addr) {
    asm volatile("ldmatrix.sync.aligned.m8n8.x4.shared.b16 {%0,%1,%2,%3}, [%4];"
                 : "=r"(r0), "=r"(r1), "=r"(r2), "=r"(r3) : "r"(addr));
}
__device__ __forceinline__ void mma_bf16(float* c, const uint32_t* a,
                                         uint32_t b0, uint32_t b1) {
    asm volatile(
        "mma.sync.aligned.m16n8k16.row.col.f32.bf16.bf16.f32 "
        "{%0,%1,%2,%3}, {%4,%5,%6,%7}, {%8,%9}, {%0,%1,%2,%3};"
        : "+f"(c[0]), "+f"(c[1]), "+f"(c[2]), "+f"(c[3])
        : "r"(a[0]), "r"(a[1]), "r"(a[2]), "r"(a[3]), "r"(b0), "r"(b1));
}

// Load one K-chunk (A:128x64 bf16, B:128x64 bf16) into SW128-swizzled SMEM.
__device__ __forceinline__ void load_stage(uint32_t sbase, int s, int k0,
                                           int bm, int bn, int tid) {
    uint32_t a0 = sbase + s * STAGE_BYTES;
    uint32_t b0 = a0 + A_BYTES;
#pragma unroll
    for (int i = 0; i < 4; i++) {            // A: 1024 x 16B units / 256 thr
        int u = tid + i * 256;
        int row = u >> 3, c = u & 7;
        uint32_t sw = swz(row * 128 + c * 16);
        cp16(a0 + sw, g_A + (size_t)(bm + row) * DIM + k0 + c * 8);
    }
#pragma unroll
    for (int i = 0; i < 4; i++) {            // B: same volume
        int u = tid + i * 256;
        int row = u >> 3, c = u & 7;
        uint32_t sw = swz(row * 128 + c * 16);
        cp16(b0 + sw, g_B + (size_t)(bn + row) * DIM + k0 + c * 8);
    }
}

// ------------- kernel 0: convert to bf16, fp32 norms, reset min -------------
__global__ void prep_kernel(const float* __restrict__ x,
                            const float* __restrict__ y, int P, int R) {
    int warp = (blockIdx.x * blockDim.x + threadIdx.x) >> 5;
    int lane = threadIdx.x & 31;
    if (blockIdx.x == 0 && threadIdx.x == 0) g_min_bits = 0xFFFFFFFFu;
    if (warp >= P + R) return;
    const float4* src4;
    uint2* dst2;
    if (warp < P) {
        src4 = (const float4*)(x + (size_t)warp * DIM);
        dst2 = (uint2*)(g_A + (size_t)warp * DIM);
    } else {
        int r = warp - P;
        src4 = (const float4*)(y + (size_t)r * DIM);
        dst2 = (uint2*)(g_B + (size_t)r * DIM);
    }
    float acc = 0.f;
#pragma unroll
    for (int j = 0; j < 4; j++) {
        float4 v = src4[lane + j * 32];
        acc += v.x * v.x + v.y * v.y + v.z * v.z + v.w * v.w;
        __nv_bfloat162 lo = __floats2bfloat162_rn(v.x, v.y);
        __nv_bfloat162 hi = __floats2bfloat162_rn(v.z, v.w);
        uint2 u;
        u.x = *reinterpret_cast<unsigned int*>(&lo);
        u.y = *reinterpret_cast<unsigned int*>(&hi);
        dst2[lane + j * 32] = u;
    }
#pragma unroll
    for (int off = 16; off > 0; off >>= 1)
        acc += __shfl_xor_sync(0xFFFFFFFFu, acc, off);
    if (lane == 0) {
        if (warp < P) g_xn[warp] = acc;
        else          g_yn[warp - P] = acc;
    }
}

// ------------- kernel 1: bf16 mma.sync GEMM + min reduction -------------
__global__ void __launch_bounds__(256, 2)
min_dist_mma_kernel(int P, int R) {
    extern __shared__ char smem[];
    uint32_t sbase = smem_u32(smem);
    const int tid = threadIdx.x;
    const int lane = tid & 31;
    const int warp = tid >> 5;
    const int wm = warp & 3;          // 0..3 : M direction (32 rows each)
    const int wn = warp >> 2;         // 0..1 : N direction (64 cols each)
    const int bm = blockIdx.y * BM;
    const int bn = blockIdx.x * BN;

    // Stage norms in SMEM for the epilogue.
    if (tid < 128)       ((float*)(smem + SOFF_XN))[tid] = g_xn[bm + tid];
    else                 ((float*)(smem + SOFF_YN))[tid - 128] = g_yn[bn + tid - 128];

    float acc[2][8][4];
#pragma unroll
    for (int i = 0; i < 2; i++)
#pragma unroll
        for (int j = 0; j < 8; j++)
#pragma unroll
            for (int r = 0; r < 4; r++) acc[i][j][r] = 0.f;

    // Prologue: prefetch chunks 0,1.
    load_stage(sbase, 0, 0, bm, bn, tid);
    asm volatile("cp.async.commit_group;" ::: "memory");
    load_stage(sbase, 1, BK, bm, bn, tid);
    asm volatile("cp.async.commit_group;" ::: "memory");

    // ldmatrix base offsets (per-lane, fixed across chunks)
    const int lrow = lane & 15;
    const int lcol = (lane >> 4) << 4;   // 0 or 16 bytes

    for (int k = 0; k < NCHUNK; k++) {
        const int s = k % STAGES;
        asm volatile("cp.async.wait_group 1;" ::: "memory");
        __syncthreads();
        if (k + 2 < NCHUNK)
            load_stage(sbase, (k + 2) % STAGES, (k + 2) * BK, bm, bn, tid);
        asm volatile("cp.async.commit_group;" ::: "memory");

        const uint32_t a0 = sbase + s * STAGE_BYTES;
        const uint32_t b0 = a0 + A_BYTES;
#pragma unroll
        for (int kk = 0; kk < 4; kk++) {          // 4 x k16 steps per chunk
            const int colb = kk * 32 + lcol;
            uint32_t af[2][4];
#pragma unroll
            for (int mi = 0; mi < 2; mi++) {
                int row = wm * 32 + mi * 16 + lrow;
                ldsm_x4(af[mi][0], af[mi][1], af[mi][2], af[mi][3],
                        a0 + swz(row * 128 + colb));
            }
            uint32_t bf[8][2];
#pragma unroll
            for (int ni2 = 0; ni2 < 4; ni2++) {   // each x4 covers 2 n8 tiles
                int row = wn * 64 + ni2 * 16 + lrow;
                uint32_t r0, r1, r2, r3;
                ldsm_x4(r0, r1, r2, r3, b0 + swz(row * 128 + colb));
                bf[ni2 * 2 + 0][0] = r0; bf[ni2 * 2 + 0][1] = r2;
                bf[ni2 * 2 + 1][0] = r1; bf[ni2 * 2 + 1][1] = r3;
            }
#pragma unroll
            for (int mi = 0; mi < 2; mi++)
#pragma unroll
                for (int ni = 0; ni < 8; ni++)
                    mma_bf16(acc[mi][ni], af[mi], bf[ni][0], bf[ni][1]);
        }
    }

    // Epilogue: sq = xn + yn - 2*dot; per-fragment min.
    const float* xs = (const float*)(smem + SOFF_XN);
    const float* ys = (const float*)(smem + SOFF_YN);
    float m = 3.4e38f;
#pragma unroll
    for (int mi = 0; mi < 2; mi++) {
        float x0 = xs[wm * 32 + mi * 16 + (lane >> 2)];
        float x1 = xs[wm * 32 + mi * 16 + (lane >> 2) + 8];
#pragma unroll
        for (int ni = 0; ni < 8; ni++) {
            float y0 = ys[wn * 64 + ni * 8 + (lane & 3) * 2];
            float y1 = ys[wn * 64 + ni * 8 + (lane & 3) * 2 + 1];
            m = fminf(m, fmaf(-2.0f, acc[mi][ni][0], x0 + y0));
            m = fminf(m, fmaf(-2.0f, acc[mi][ni][1], x0 + y1));
            m = fminf(m, fmaf(-2.0f, acc[mi][ni][2], x1 + y0));
            m = fminf(m, fmaf(-2.0f, acc[mi][ni][3], x1 + y1));
        }
    }
#pragma unroll
    for (int off = 16; off > 0; off >>= 1)
        m = fminf(m, __shfl_xor_sync(0xFFFFFFFFu, m, off));
    if (lane == 0) atomicMin(&g_min_bits, enc_f(m));
}

// ------------- kernel 2: finalize -------------
__global__ void finalize_kernel(float* __restrict__ out) {
    out[0] = sqrtf(fmaxf(dec_f(g_min_bits), 0.0f));
}

extern "C" void kernel_launch(void* const* d_in, const int* in_sizes, int n_in,
                              void* d_out, int out_size) {
    const float* x = (const float*)d_in[0];  // [1, P, 512] fp32
    const float* y = (const float*)d_in[1];  // [1, R, 512] fp32
    int P = in_sizes[0] / DIM;
    int R = in_sizes[1] / DIM;

    int rows = P + R;  // one warp per row
    prep_kernel<<<(rows * 32 + 255) / 256, 256>>>(x, y, P, R);

    cudaFuncSetAttribute(min_dist_mma_kernel,
                         cudaFuncAttributeMaxDynamicSharedMemorySize, SMEM_BYTES);
    dim3 grid(R / BN, P / BM);  // (512, 16) = 8192 CTAs
    min_dist_mma_kernel<<<grid, 256, SMEM_BYTES>>>(P, R);

    finalize_kernel<<<1, 1>>>((float*)d_out);
}